// round 12
// baseline (speedup 1.0000x reference)
#include <cuda_runtime.h>
#include <cstdint>

#define B_    64
#define T_    2048
#define DIN   256
#define DH    256
#define DC    256
#define DOUT  256
#define G3    768   // 3 gates * 256

// Scratch (allocation-free rule: __device__ globals)
__device__ float g_Gx[(size_t)B_ * T_ * G3];  // x-part gate preactivations (+bias)
__device__ float g_H [(size_t)B_ * T_ * DH];  // h_t for all t (for output GEMM)

// ---------------- helpers ----------------

__device__ __forceinline__ float2 ffma2(float2 a, float2 b, float2 c) {
    union U { float2 f; unsigned long long u; };
    U ua, ub, uc, ud;
    ua.f = a; ub.f = b; uc.f = c;
    asm("fma.rn.f32x2 %0, %1, %2, %3;"
        : "=l"(ud.u) : "l"(ua.u), "l"(ub.u), "l"(uc.u));
    return ud.f;
}

__device__ __forceinline__ uint32_t smem_u32(const void* p) {
    uint32_t a;
    asm("{ .reg .u64 t; cvta.to.shared.u64 t, %1; cvt.u32.u64 %0, t; }"
        : "=r"(a) : "l"(p));
    return a;
}

__device__ __forceinline__ void cluster_sync_() {
    asm volatile("barrier.cluster.arrive.aligned;" ::: "memory");
    asm volatile("barrier.cluster.wait.aligned;" ::: "memory");
}

__device__ __forceinline__ void mbar_init1(uint32_t mbar) {
    asm volatile("mbarrier.init.shared.b64 [%0], %1;" :: "r"(mbar), "r"(1u) : "memory");
}

__device__ __forceinline__ void mbar_expect(uint32_t mbar, uint32_t bytes) {
    asm volatile("mbarrier.arrive.expect_tx.shared.b64 _, [%0], %1;"
                 :: "r"(mbar), "r"(bytes) : "memory");
}

__device__ __forceinline__ void mbar_wait(uint32_t mbar, uint32_t parity) {
    asm volatile(
        "{\n\t"
        ".reg .pred P;\n"
        "W%=:\n\t"
        "mbarrier.try_wait.parity.acquire.cta.shared::cta.b64 P, [%0], %1, 0x989680;\n\t"
        "@P bra.uni D%=;\n\t"
        "bra.uni W%=;\n"
        "D%=:\n\t"
        "}"
        :: "r"(mbar), "r"(parity) : "memory");
}

// store one f32 into rank's smem + count 4 tx bytes on that rank's mbarrier
__device__ __forceinline__ void st_async_remote(uint32_t laddr, uint32_t lmbar,
                                                uint32_t rank, float v) {
    asm volatile(
        "{\n\t"
        ".reg .b32 ra, rb;\n\t"
        "mapa.shared::cluster.u32 ra, %0, %2;\n\t"
        "mapa.shared::cluster.u32 rb, %1, %2;\n\t"
        "st.async.shared::cluster.mbarrier::complete_tx::bytes.b32 [ra], %3, [rb];\n\t"
        "}"
        :: "r"(laddr), "r"(lmbar), "r"(rank), "r"(__float_as_uint(v)) : "memory");
}

__device__ __forceinline__ float sigmoidf_(float x) {
    return __fdividef(1.0f, 1.0f + __expf(-x));
}

__device__ __forceinline__ float tanhf_(float x) {
    return 1.0f - __fdividef(2.0f, 1.0f + __expf(2.0f * x));
}

// ================= GEMM core: 128x128 tile, BK=16, double-buffered (R9 proven) =======

__global__ __launch_bounds__(256) void gemm_gx(
    const float* __restrict__ X,
    const float* __restrict__ Wf, const float* __restrict__ Wi, const float* __restrict__ Wo,
    const float* __restrict__ bf, const float* __restrict__ bi, const float* __restrict__ bo,
    const int* __restrict__ Np)
{
    const int N = *Np;
    const int m0 = blockIdx.y * 128;
    if (m0 >= B_ * N) return;
    const int j0v = blockIdx.x * 128;
    const int g  = j0v >> 8;
    const int d0 = j0v & 255;
    const float* Wg = (g == 0) ? Wf : ((g == 1) ? Wi : Wo);
    const float* bg = (g == 0) ? bf : ((g == 1) ? bi : bo);

    __shared__ float2 As2[2][8][128];
    __shared__ float2 Bs2[2][8][128];

    const int tid = threadIdx.x;
    const int tx = tid & 15, ty = tid >> 4;

    const int ra = tid >> 1, ha = tid & 1;
    int mg = m0 + ra; if (mg >= B_ * N) mg = B_ * N - 1;
    const int bb = mg / N, tt = mg % N;
    const float* arow = X + (size_t)(bb * T_ + tt) * DIN + 8 * ha;

    const int kp0 = tid >> 5;
    const int np0 = tid & 31;
    const float* bcol = Wg + d0 + 2 * np0;

    float4 a0, a1;
    float2 v00, v01, v10, v11;

    a0 = *reinterpret_cast<const float4*>(arow);
    a1 = *reinterpret_cast<const float4*>(arow + 4);
    v00 = *reinterpret_cast<const float2*>(bcol + (size_t)(2 * kp0) * DC);
    v01 = *reinterpret_cast<const float2*>(bcol + (size_t)(2 * kp0 + 1) * DC);
    v10 = *reinterpret_cast<const float2*>(bcol + (size_t)(2 * kp0) * DC + 64);
    v11 = *reinterpret_cast<const float2*>(bcol + (size_t)(2 * kp0 + 1) * DC + 64);

    As2[0][4 * ha + 0][ra] = make_float2(a0.x, a0.y);
    As2[0][4 * ha + 1][ra] = make_float2(a0.z, a0.w);
    As2[0][4 * ha + 2][ra] = make_float2(a1.x, a1.y);
    As2[0][4 * ha + 3][ra] = make_float2(a1.z, a1.w);
    *reinterpret_cast<float4*>(&Bs2[0][kp0][2 * np0]) =
        make_float4(v00.x, v01.x, v00.y, v01.y);
    *reinterpret_cast<float4*>(&Bs2[0][kp0][2 * np0 + 64]) =
        make_float4(v10.x, v11.x, v10.y, v11.y);
    __syncthreads();

    float2 acc[8][8];
    #pragma unroll
    for (int i = 0; i < 8; i++)
        #pragma unroll
        for (int j = 0; j < 8; j++) acc[i][j] = make_float2(0.f, 0.f);

    #pragma unroll 1
    for (int c = 0; c < 16; ++c) {
        const int buf = c & 1;
        if (c + 1 < 16) {
            const int kk = (c + 1) * 16;
            a0 = *reinterpret_cast<const float4*>(arow + kk);
            a1 = *reinterpret_cast<const float4*>(arow + kk + 4);
            v00 = *reinterpret_cast<const float2*>(bcol + (size_t)(kk + 2 * kp0) * DC);
            v01 = *reinterpret_cast<const float2*>(bcol + (size_t)(kk + 2 * kp0 + 1) * DC);
            v10 = *reinterpret_cast<const float2*>(bcol + (size_t)(kk + 2 * kp0) * DC + 64);
            v11 = *reinterpret_cast<const float2*>(bcol + (size_t)(kk + 2 * kp0 + 1) * DC + 64);
        }
        #pragma unroll
        for (int kp = 0; kp < 8; kp++) {
            float2 a2[8], b2[8];
            #pragma unroll
            for (int i = 0; i < 4; i++) {
                float4 t = *reinterpret_cast<const float4*>(&As2[buf][kp][32 * i + 2 * ty]);
                a2[2 * i]     = make_float2(t.x, t.y);
                a2[2 * i + 1] = make_float2(t.z, t.w);
            }
            #pragma unroll
            for (int j = 0; j < 4; j++) {
                float4 t = *reinterpret_cast<const float4*>(&Bs2[buf][kp][32 * j + 2 * tx]);
                b2[2 * j]     = make_float2(t.x, t.y);
                b2[2 * j + 1] = make_float2(t.z, t.w);
            }
            #pragma unroll
            for (int i = 0; i < 8; i++)
                #pragma unroll
                for (int j = 0; j < 8; j++)
                    acc[i][j] = ffma2(a2[i], b2[j], acc[i][j]);
        }
        if (c + 1 < 16) {
            const int nb = buf ^ 1;
            As2[nb][4 * ha + 0][ra] = make_float2(a0.x, a0.y);
            As2[nb][4 * ha + 1][ra] = make_float2(a0.z, a0.w);
            As2[nb][4 * ha + 2][ra] = make_float2(a1.x, a1.y);
            As2[nb][4 * ha + 3][ra] = make_float2(a1.z, a1.w);
            *reinterpret_cast<float4*>(&Bs2[nb][kp0][2 * np0]) =
                make_float4(v00.x, v01.x, v00.y, v01.y);
            *reinterpret_cast<float4*>(&Bs2[nb][kp0][2 * np0 + 64]) =
                make_float4(v10.x, v11.x, v10.y, v11.y);
        }
        __syncthreads();
    }

    float bgv[8];
    #pragma unroll
    for (int u = 0; u < 4; u++) {
        bgv[2 * u]     = bg[d0 + 32 * u + 2 * tx];
        bgv[2 * u + 1] = bg[d0 + 32 * u + 2 * tx + 1];
    }
    #pragma unroll
    for (int i = 0; i < 8; i++) {
        const int m = m0 + 32 * (i >> 1) + 2 * ty + (i & 1);
        if (m < B_ * N) {
            float* crow = g_Gx + (size_t)m * G3 + j0v;
            #pragma unroll
            for (int u = 0; u < 4; u++)
                *reinterpret_cast<float2*>(crow + 32 * u + 2 * tx) =
                    make_float2(acc[i][2 * u].x + acc[i][2 * u].y + bgv[2 * u],
                                acc[i][2 * u + 1].x + acc[i][2 * u + 1].y + bgv[2 * u + 1]);
        }
    }
}

// ---------------- GEMM 3: outs = sigmoid(H @ Wout + bout) ----------------

__global__ __launch_bounds__(256) void gemm_out(
    const float* __restrict__ Wout, const float* __restrict__ bout,
    float* __restrict__ out, const int* __restrict__ Np)
{
    const int N = *Np;
    const int m0 = blockIdx.y * 128;
    if (m0 >= B_ * N) return;
    const int j0v = blockIdx.x * 128;

    __shared__ float2 As2[2][8][128];
    __shared__ float2 Bs2[2][8][128];

    const int tid = threadIdx.x;
    const int tx = tid & 15, ty = tid >> 4;

    const int ra = tid >> 1, ha = tid & 1;
    int mg = m0 + ra; if (mg >= B_ * N) mg = B_ * N - 1;
    const float* arow = g_H + (size_t)mg * DH + 8 * ha;

    const int kp0 = tid >> 5;
    const int np0 = tid & 31;
    const float* bcol = Wout + j0v + 2 * np0;

    float4 a0, a1;
    float2 v00, v01, v10, v11;

    a0 = *reinterpret_cast<const float4*>(arow);
    a1 = *reinterpret_cast<const float4*>(arow + 4);
    v00 = *reinterpret_cast<const float2*>(bcol + (size_t)(2 * kp0) * DOUT);
    v01 = *reinterpret_cast<const float2*>(bcol + (size_t)(2 * kp0 + 1) * DOUT);
    v10 = *reinterpret_cast<const float2*>(bcol + (size_t)(2 * kp0) * DOUT + 64);
    v11 = *reinterpret_cast<const float2*>(bcol + (size_t)(2 * kp0 + 1) * DOUT + 64);

    As2[0][4 * ha + 0][ra] = make_float2(a0.x, a0.y);
    As2[0][4 * ha + 1][ra] = make_float2(a0.z, a0.w);
    As2[0][4 * ha + 2][ra] = make_float2(a1.x, a1.y);
    As2[0][4 * ha + 3][ra] = make_float2(a1.z, a1.w);
    *reinterpret_cast<float4*>(&Bs2[0][kp0][2 * np0]) =
        make_float4(v00.x, v01.x, v00.y, v01.y);
    *reinterpret_cast<float4*>(&Bs2[0][kp0][2 * np0 + 64]) =
        make_float4(v10.x, v11.x, v10.y, v11.y);
    __syncthreads();

    float2 acc[8][8];
    #pragma unroll
    for (int i = 0; i < 8; i++)
        #pragma unroll
        for (int j = 0; j < 8; j++) acc[i][j] = make_float2(0.f, 0.f);

    #pragma unroll 1
    for (int c = 0; c < 16; ++c) {
        const int buf = c & 1;
        if (c + 1 < 16) {
            const int kk = (c + 1) * 16;
            a0 = *reinterpret_cast<const float4*>(arow + kk);
            a1 = *reinterpret_cast<const float4*>(arow + kk + 4);
            v00 = *reinterpret_cast<const float2*>(bcol + (size_t)(kk + 2 * kp0) * DOUT);
            v01 = *reinterpret_cast<const float2*>(bcol + (size_t)(kk + 2 * kp0 + 1) * DOUT);
            v10 = *reinterpret_cast<const float2*>(bcol + (size_t)(kk + 2 * kp0) * DOUT + 64);
            v11 = *reinterpret_cast<const float2*>(bcol + (size_t)(kk + 2 * kp0 + 1) * DOUT + 64);
        }
        #pragma unroll
        for (int kp = 0; kp < 8; kp++) {
            float2 a2[8], b2[8];
            #pragma unroll
            for (int i = 0; i < 4; i++) {
                float4 t = *reinterpret_cast<const float4*>(&As2[buf][kp][32 * i + 2 * ty]);
                a2[2 * i]     = make_float2(t.x, t.y);
                a2[2 * i + 1] = make_float2(t.z, t.w);
            }
            #pragma unroll
            for (int j = 0; j < 4; j++) {
                float4 t = *reinterpret_cast<const float4*>(&Bs2[buf][kp][32 * j + 2 * tx]);
                b2[2 * j]     = make_float2(t.x, t.y);
                b2[2 * j + 1] = make_float2(t.z, t.w);
            }
            #pragma unroll
            for (int i = 0; i < 8; i++)
                #pragma unroll
                for (int j = 0; j < 8; j++)
                    acc[i][j] = ffma2(a2[i], b2[j], acc[i][j]);
        }
        if (c + 1 < 16) {
            const int nb = buf ^ 1;
            As2[nb][4 * ha + 0][ra] = make_float2(a0.x, a0.y);
            As2[nb][4 * ha + 1][ra] = make_float2(a0.z, a0.w);
            As2[nb][4 * ha + 2][ra] = make_float2(a1.x, a1.y);
            As2[nb][4 * ha + 3][ra] = make_float2(a1.z, a1.w);
            *reinterpret_cast<float4*>(&Bs2[nb][kp0][2 * np0]) =
                make_float4(v00.x, v01.x, v00.y, v01.y);
            *reinterpret_cast<float4*>(&Bs2[nb][kp0][2 * np0 + 64]) =
                make_float4(v10.x, v11.x, v10.y, v11.y);
        }
        __syncthreads();
    }

    float bgv[8];
    #pragma unroll
    for (int u = 0; u < 4; u++) {
        bgv[2 * u]     = bout[j0v + 32 * u + 2 * tx];
        bgv[2 * u + 1] = bout[j0v + 32 * u + 2 * tx + 1];
    }
    #pragma unroll
    for (int i = 0; i < 8; i++) {
        const int m = m0 + 32 * (i >> 1) + 2 * ty + (i & 1);
        if (m < B_ * N) {
            float* crow = out + (size_t)m * DOUT + j0v;
            #pragma unroll
            for (int u = 0; u < 4; u++)
                *reinterpret_cast<float2*>(crow + 32 * u + 2 * tx) =
                    make_float2(
                        sigmoidf_(acc[i][2 * u].x + acc[i][2 * u].y + bgv[2 * u]),
                        sigmoidf_(acc[i][2 * u + 1].x + acc[i][2 * u + 1].y + bgv[2 * u + 1]));
        }
    }
}

// ---------------- Recurrence: batch-STAGGERED, 4-CTA clusters ----------------
// As R9 (quarter-split GEMV, st.async transport) but the two batches of a cluster are
// processed as separate phases with separate per-batch mbarriers. Batch b's send->wait
// DSMEM round trip is hidden behind batch (1-b)'s compute phase, removing the delivery
// latency from the critical path. 2 shuffles/batch reduction; expect_tx = 1024 B/batch.

__global__ __launch_bounds__(384, 1) __cluster_dims__(4, 1, 1)
void lstm_rec(
    const float* __restrict__ h0, const float* __restrict__ c0,
    const float* __restrict__ Wf, const float* __restrict__ Wi, const float* __restrict__ Wo,
    float* __restrict__ out, const int* __restrict__ Np)
{
    const int N   = *Np;
    const int r   = blockIdx.x & 3;
    const int cid = blockIdx.x >> 2;
    const int b0  = cid * 2;
    const int tid = threadIdx.x;

    __shared__ __align__(16) float h_s[2][2][256];   // [parity][batch][dim]
    __shared__ float pre_s[2][208];                  // [batch][col]
    __shared__ __align__(8) unsigned long long mbar[2][2];   // [batch][parity]

    const int lane = tid & 31;
    const int wrp  = tid >> 5;
    const int kq   = lane & 3;                        // k-interleave slot
    const int cc0  = wrp * 16 + ((lane >> 2) << 1);   // first of 2 local gate-cols
    const int g0   = cc0 >> 6;
    const int gd0  = r * 64 + (cc0 & 63);
    const float* Wg = (g0 == 0) ? Wf : ((g0 == 1) ? Wi : Wo);

    // weights: w0/w1 = cols cc0/cc0+1; per line li: k0 = 4*kq + 16*li (h-part rows +256)
    float2 w0[32], w1[32];
    #pragma unroll
    for (int li = 0; li < 16; li++) {
        const int k0 = 4 * kq + 16 * li;
        const float* p0 = Wg + (size_t)(256 + k0) * DC + gd0;
        w0[2 * li]     = make_float2(p0[0],          p0[DC]);
        w0[2 * li + 1] = make_float2(p0[2 * DC],     p0[3 * DC]);
        w1[2 * li]     = make_float2(p0[1],          p0[DC + 1]);
        w1[2 * li + 1] = make_float2(p0[2 * DC + 1], p0[3 * DC + 1]);
    }

    // writer identity: lanes kq<2 write col cwz (for whichever batch is in phase)
    const bool is_writer = (kq < 2);
    const int cwz   = cc0 + (kq & 1);
    const int gcolz = (cwz >> 6) * 256 + r * 64 + (cwz & 63);

    const uint32_t mbA[2] = { smem_u32(&mbar[0][0]), smem_u32(&mbar[0][1]) };
    const uint32_t mbB[2] = { smem_u32(&mbar[1][0]), smem_u32(&mbar[1][1]) };
    if (tid == 0) {
        #pragma unroll
        for (int b = 0; b < 2; b++)
            #pragma unroll
            for (int p = 0; p < 2; p++) {
                const uint32_t m = (b == 0) ? mbA[p] : mbB[p];
                mbar_init1(m);
                mbar_expect(m, 1024u);
            }
    }

    // init h (parity 0)
    for (int i = tid; i < 512; i += 384) {
        const int b = i >> 8, d = i & 255;
        h_s[0][b][d] = h0[(b0 + b) * DH + d];
    }
    float c_st = 0.f, h_loc = 0.f;
    const int ob = (tid < 128) ? (tid >> 6) : 0;     // owner batch
    const int pd = (tid < 128) ? (tid & 63) : 0;
    if (tid < 128) c_st = c0[(b0 + ob) * DC + r * 64 + pd];
    __syncthreads();
    cluster_sync_();   // all mbarriers initialized before any DSMEM traffic

    // gx prefetch (writers only need it)
    float gxv[2];
    gxv[0] = g_Gx[((size_t)(b0 + 0) * N + 0) * G3 + gcolz];
    gxv[1] = g_Gx[((size_t)(b0 + 1) * N + 0) * G3 + gcolz];

    float* out_hf = out + (size_t)B_ * N * DOUT;
    float* out_cf = out_hf + B_ * DH;

    int ph[2][2] = { {0, 0}, {0, 0} };   // [batch][parity]

    for (int t = 0; t < N; t++) {
        const int p = t & 1;
        const int tn = (t + 1 < N) ? (t + 1) : t;

        #pragma unroll
        for (int b = 0; b < 2; b++) {
            const uint32_t mb_rd = (b == 0) ? mbA[p] : mbB[p];
            const uint32_t mb_wr = (b == 0) ? mbA[1 - p] : mbB[1 - p];

            if (t > 0) {
                mbar_wait(mb_rd, (uint32_t)ph[b][p]);
                ph[b][p] ^= 1;
                if (tid == 0) mbar_expect(mb_rd, 1024u);   // re-arm for step t+2
            }

            const float gxc = gxv[b];
            gxv[b] = g_Gx[((size_t)(b0 + b) * N + tn) * G3 + gcolz];

            // GEMV for batch b: 2 cols over this lane's k-subset
            float2 a0 = make_float2(0.f, 0.f), a1 = a0;
            {
                const float4* hb = reinterpret_cast<const float4*>(&h_s[p][b][4 * kq]);
                #pragma unroll
                for (int li = 0; li < 16; li++) {
                    float4 hv = hb[4 * li];
                    float2 hlo = make_float2(hv.x, hv.y), hhi = make_float2(hv.z, hv.w);
                    a0 = ffma2(hlo, w0[2 * li], a0);
                    a0 = ffma2(hhi, w0[2 * li + 1], a0);
                    a1 = ffma2(hlo, w1[2 * li], a1);
                    a1 = ffma2(hhi, w1[2 * li + 1], a1);
                }
            }
            const float v0 = a0.x + a0.y;
            const float v1 = a1.x + a1.y;

            // reduce across kq: round 1 (xor 1) packs col0/col1 by kq bit0
            const bool bit0 = (kq & 1);
            float send1 = bit0 ? v0 : v1, keep1 = bit0 ? v1 : v0;
            float ts = keep1 + __shfl_xor_sync(0xffffffffu, send1, 1);
            // round 2 (xor 2) completes the k-sum
            ts += __shfl_xor_sync(0xffffffffu, ts, 2);

            if (is_writer) pre_s[b][cwz] = ts + gxc;
            __syncthreads();

            // owners of batch b: threads [64b, 64b+64)
            if ((tid >> 6) == b && tid < 128) {
                const float pf = pre_s[b][pd];
                const float pi = pre_s[b][64 + pd];
                const float po = pre_s[b][128 + pd];
                const float f  = sigmoidf_(pf);
                const float ig = sigmoidf_(pi);
                const float z  = tanhf_(pi);
                const float o  = sigmoidf_(po);
                c_st  = c_st * f + z * ig;
                h_loc = tanhf_(c_st) * o;

                if (t + 1 < N) {
                    const uint32_t la = smem_u32(&h_s[1 - p][b][r * 64 + pd]);
                    st_async_remote(la, mb_wr, 0u, h_loc);
                    st_async_remote(la, mb_wr, 1u, h_loc);
                    st_async_remote(la, mb_wr, 2u, h_loc);
                    st_async_remote(la, mb_wr, 3u, h_loc);
                }
                g_H[((size_t)(b0 + b) * N + t) * DH + r * 64 + pd] = h_loc;
            }
        }
    }

    if (tid < 128) {
        out_hf[(b0 + ob) * DH + r * 64 + pd] = h_loc;
        out_cf[(b0 + ob) * DC + r * 64 + pd] = c_st;
    }
    cluster_sync_();   // no CTA exits while peers could still be mid-step
}

// ---------------- launch ----------------

extern "C" void kernel_launch(void* const* d_in, const int* in_sizes, int n_in,
                              void* d_out, int out_size) {
    const float* x    = (const float*)d_in[0];
    const float* h0   = (const float*)d_in[1];
    const float* c0   = (const float*)d_in[2];
    const float* Wf   = (const float*)d_in[3];
    const float* bfp  = (const float*)d_in[4];
    const float* Wi   = (const float*)d_in[5];
    const float* bip  = (const float*)d_in[6];
    const float* Wo   = (const float*)d_in[7];
    const float* bop  = (const float*)d_in[8];
    const float* Wout = (const float*)d_in[9];
    const float* bout = (const float*)d_in[10];
    const int*   Np   = (const int*)d_in[11];
    float* out = (float*)d_out;

    dim3 g1(G3 / 128, B_ * T_ / 128);
    gemm_gx<<<g1, 256>>>(x, Wf, Wi, Wo, bfp, bip, bop, Np);

    lstm_rec<<<128, 384>>>(h0, c0, Wf, Wi, Wo, out, Np);

    dim3 g3(DOUT / 128, B_ * T_ / 128);
    gemm_out<<<g3, 256>>>(Wout, bout, out, Np);
}

// round 15
// speedup vs baseline: 1.0745x; 1.0745x over previous
#include <cuda_runtime.h>
#include <cstdint>

#define B_    64
#define T_    2048
#define DIN   256
#define DH    256
#define DC    256
#define DOUT  256
#define G3    768   // 3 gates * 256

// Scratch (allocation-free rule: __device__ globals)
__device__ float g_Gx[(size_t)B_ * T_ * G3];  // x-part gate preactivations (+bias)
__device__ float g_H [(size_t)B_ * T_ * DH];  // h_t for all t (for output GEMM)

// ---------------- helpers ----------------

__device__ __forceinline__ float2 ffma2(float2 a, float2 b, float2 c) {
    union U { float2 f; unsigned long long u; };
    U ua, ub, uc, ud;
    ua.f = a; ub.f = b; uc.f = c;
    asm("fma.rn.f32x2 %0, %1, %2, %3;"
        : "=l"(ud.u) : "l"(ua.u), "l"(ub.u), "l"(uc.u));
    return ud.f;
}

__device__ __forceinline__ uint32_t smem_u32(const void* p) {
    uint32_t a;
    asm("{ .reg .u64 t; cvta.to.shared.u64 t, %1; cvt.u32.u64 %0, t; }"
        : "=r"(a) : "l"(p));
    return a;
}

__device__ __forceinline__ void cluster_sync_() {
    asm volatile("barrier.cluster.arrive.aligned;" ::: "memory");
    asm volatile("barrier.cluster.wait.aligned;" ::: "memory");
}

__device__ __forceinline__ void mbar_init1(uint32_t mbar) {
    asm volatile("mbarrier.init.shared.b64 [%0], %1;" :: "r"(mbar), "r"(1u) : "memory");
}

__device__ __forceinline__ void mbar_expect(uint32_t mbar, uint32_t bytes) {
    asm volatile("mbarrier.arrive.expect_tx.shared.b64 _, [%0], %1;"
                 :: "r"(mbar), "r"(bytes) : "memory");
}

__device__ __forceinline__ void mbar_wait(uint32_t mbar, uint32_t parity) {
    asm volatile(
        "{\n\t"
        ".reg .pred P;\n"
        "W%=:\n\t"
        "mbarrier.try_wait.parity.acquire.cta.shared::cta.b64 P, [%0], %1, 0x989680;\n\t"
        "@P bra.uni D%=;\n\t"
        "bra.uni W%=;\n"
        "D%=:\n\t"
        "}"
        :: "r"(mbar), "r"(parity) : "memory");
}

// store one packed f32x2 (b64) into rank's smem + count 8 tx bytes on its mbarrier
__device__ __forceinline__ void st_async_remote64(uint32_t laddr, uint32_t lmbar,
                                                  uint32_t rank, unsigned long long v) {
    asm volatile(
        "{\n\t"
        ".reg .b32 ra, rb;\n\t"
        "mapa.shared::cluster.u32 ra, %0, %2;\n\t"
        "mapa.shared::cluster.u32 rb, %1, %2;\n\t"
        "st.async.shared::cluster.mbarrier::complete_tx::bytes.b64 [ra], %3, [rb];\n\t"
        "}"
        :: "r"(laddr), "r"(lmbar), "r"(rank), "l"(v) : "memory");
}

__device__ __forceinline__ float sigmoidf_(float x) {
    return __fdividef(1.0f, 1.0f + __expf(-x));
}

__device__ __forceinline__ float tanhf_(float x) {
    return 1.0f - __fdividef(2.0f, 1.0f + __expf(2.0f * x));
}

// ================= GEMM core: 128x128 tile, BK=16, double-buffered (R9 proven) =======

__global__ __launch_bounds__(256) void gemm_gx(
    const float* __restrict__ X,
    const float* __restrict__ Wf, const float* __restrict__ Wi, const float* __restrict__ Wo,
    const float* __restrict__ bf, const float* __restrict__ bi, const float* __restrict__ bo,
    const int* __restrict__ Np)
{
    const int N = *Np;
    const int m0 = blockIdx.y * 128;
    if (m0 >= B_ * N) return;
    const int j0v = blockIdx.x * 128;
    const int g  = j0v >> 8;
    const int d0 = j0v & 255;
    const float* Wg = (g == 0) ? Wf : ((g == 1) ? Wi : Wo);
    const float* bg = (g == 0) ? bf : ((g == 1) ? bi : bo);

    __shared__ float2 As2[2][8][128];
    __shared__ float2 Bs2[2][8][128];

    const int tid = threadIdx.x;
    const int tx = tid & 15, ty = tid >> 4;

    const int ra = tid >> 1, ha = tid & 1;
    int mg = m0 + ra; if (mg >= B_ * N) mg = B_ * N - 1;
    const int bb = mg / N, tt = mg % N;
    const float* arow = X + (size_t)(bb * T_ + tt) * DIN + 8 * ha;

    const int kp0 = tid >> 5;
    const int np0 = tid & 31;
    const float* bcol = Wg + d0 + 2 * np0;

    float4 a0, a1;
    float2 v00, v01, v10, v11;

    a0 = *reinterpret_cast<const float4*>(arow);
    a1 = *reinterpret_cast<const float4*>(arow + 4);
    v00 = *reinterpret_cast<const float2*>(bcol + (size_t)(2 * kp0) * DC);
    v01 = *reinterpret_cast<const float2*>(bcol + (size_t)(2 * kp0 + 1) * DC);
    v10 = *reinterpret_cast<const float2*>(bcol + (size_t)(2 * kp0) * DC + 64);
    v11 = *reinterpret_cast<const float2*>(bcol + (size_t)(2 * kp0 + 1) * DC + 64);

    As2[0][4 * ha + 0][ra] = make_float2(a0.x, a0.y);
    As2[0][4 * ha + 1][ra] = make_float2(a0.z, a0.w);
    As2[0][4 * ha + 2][ra] = make_float2(a1.x, a1.y);
    As2[0][4 * ha + 3][ra] = make_float2(a1.z, a1.w);
    *reinterpret_cast<float4*>(&Bs2[0][kp0][2 * np0]) =
        make_float4(v00.x, v01.x, v00.y, v01.y);
    *reinterpret_cast<float4*>(&Bs2[0][kp0][2 * np0 + 64]) =
        make_float4(v10.x, v11.x, v10.y, v11.y);
    __syncthreads();

    float2 acc[8][8];
    #pragma unroll
    for (int i = 0; i < 8; i++)
        #pragma unroll
        for (int j = 0; j < 8; j++) acc[i][j] = make_float2(0.f, 0.f);

    #pragma unroll 1
    for (int c = 0; c < 16; ++c) {
        const int buf = c & 1;
        if (c + 1 < 16) {
            const int kk = (c + 1) * 16;
            a0 = *reinterpret_cast<const float4*>(arow + kk);
            a1 = *reinterpret_cast<const float4*>(arow + kk + 4);
            v00 = *reinterpret_cast<const float2*>(bcol + (size_t)(kk + 2 * kp0) * DC);
            v01 = *reinterpret_cast<const float2*>(bcol + (size_t)(kk + 2 * kp0 + 1) * DC);
            v10 = *reinterpret_cast<const float2*>(bcol + (size_t)(kk + 2 * kp0) * DC + 64);
            v11 = *reinterpret_cast<const float2*>(bcol + (size_t)(kk + 2 * kp0 + 1) * DC + 64);
        }
        #pragma unroll
        for (int kp = 0; kp < 8; kp++) {
            float2 a2[8], b2[8];
            #pragma unroll
            for (int i = 0; i < 4; i++) {
                float4 t = *reinterpret_cast<const float4*>(&As2[buf][kp][32 * i + 2 * ty]);
                a2[2 * i]     = make_float2(t.x, t.y);
                a2[2 * i + 1] = make_float2(t.z, t.w);
            }
            #pragma unroll
            for (int j = 0; j < 4; j++) {
                float4 t = *reinterpret_cast<const float4*>(&Bs2[buf][kp][32 * j + 2 * tx]);
                b2[2 * j]     = make_float2(t.x, t.y);
                b2[2 * j + 1] = make_float2(t.z, t.w);
            }
            #pragma unroll
            for (int i = 0; i < 8; i++)
                #pragma unroll
                for (int j = 0; j < 8; j++)
                    acc[i][j] = ffma2(a2[i], b2[j], acc[i][j]);
        }
        if (c + 1 < 16) {
            const int nb = buf ^ 1;
            As2[nb][4 * ha + 0][ra] = make_float2(a0.x, a0.y);
            As2[nb][4 * ha + 1][ra] = make_float2(a0.z, a0.w);
            As2[nb][4 * ha + 2][ra] = make_float2(a1.x, a1.y);
            As2[nb][4 * ha + 3][ra] = make_float2(a1.z, a1.w);
            *reinterpret_cast<float4*>(&Bs2[nb][kp0][2 * np0]) =
                make_float4(v00.x, v01.x, v00.y, v01.y);
            *reinterpret_cast<float4*>(&Bs2[nb][kp0][2 * np0 + 64]) =
                make_float4(v10.x, v11.x, v10.y, v11.y);
        }
        __syncthreads();
    }

    float bgv[8];
    #pragma unroll
    for (int u = 0; u < 4; u++) {
        bgv[2 * u]     = bg[d0 + 32 * u + 2 * tx];
        bgv[2 * u + 1] = bg[d0 + 32 * u + 2 * tx + 1];
    }
    #pragma unroll
    for (int i = 0; i < 8; i++) {
        const int m = m0 + 32 * (i >> 1) + 2 * ty + (i & 1);
        if (m < B_ * N) {
            float* crow = g_Gx + (size_t)m * G3 + j0v;
            #pragma unroll
            for (int u = 0; u < 4; u++)
                *reinterpret_cast<float2*>(crow + 32 * u + 2 * tx) =
                    make_float2(acc[i][2 * u].x + acc[i][2 * u].y + bgv[2 * u],
                                acc[i][2 * u + 1].x + acc[i][2 * u + 1].y + bgv[2 * u + 1]);
        }
    }
}

// ---------------- GEMM 3: outs = sigmoid(H @ Wout + bout) ----------------

__global__ __launch_bounds__(256) void gemm_out(
    const float* __restrict__ Wout, const float* __restrict__ bout,
    float* __restrict__ out, const int* __restrict__ Np)
{
    const int N = *Np;
    const int m0 = blockIdx.y * 128;
    if (m0 >= B_ * N) return;
    const int j0v = blockIdx.x * 128;

    __shared__ float2 As2[2][8][128];
    __shared__ float2 Bs2[2][8][128];

    const int tid = threadIdx.x;
    const int tx = tid & 15, ty = tid >> 4;

    const int ra = tid >> 1, ha = tid & 1;
    int mg = m0 + ra; if (mg >= B_ * N) mg = B_ * N - 1;
    const float* arow = g_H + (size_t)mg * DH + 8 * ha;

    const int kp0 = tid >> 5;
    const int np0 = tid & 31;
    const float* bcol = Wout + j0v + 2 * np0;

    float4 a0, a1;
    float2 v00, v01, v10, v11;

    a0 = *reinterpret_cast<const float4*>(arow);
    a1 = *reinterpret_cast<const float4*>(arow + 4);
    v00 = *reinterpret_cast<const float2*>(bcol + (size_t)(2 * kp0) * DOUT);
    v01 = *reinterpret_cast<const float2*>(bcol + (size_t)(2 * kp0 + 1) * DOUT);
    v10 = *reinterpret_cast<const float2*>(bcol + (size_t)(2 * kp0) * DOUT + 64);
    v11 = *reinterpret_cast<const float2*>(bcol + (size_t)(2 * kp0 + 1) * DOUT + 64);

    As2[0][4 * ha + 0][ra] = make_float2(a0.x, a0.y);
    As2[0][4 * ha + 1][ra] = make_float2(a0.z, a0.w);
    As2[0][4 * ha + 2][ra] = make_float2(a1.x, a1.y);
    As2[0][4 * ha + 3][ra] = make_float2(a1.z, a1.w);
    *reinterpret_cast<float4*>(&Bs2[0][kp0][2 * np0]) =
        make_float4(v00.x, v01.x, v00.y, v01.y);
    *reinterpret_cast<float4*>(&Bs2[0][kp0][2 * np0 + 64]) =
        make_float4(v10.x, v11.x, v10.y, v11.y);
    __syncthreads();

    float2 acc[8][8];
    #pragma unroll
    for (int i = 0; i < 8; i++)
        #pragma unroll
        for (int j = 0; j < 8; j++) acc[i][j] = make_float2(0.f, 0.f);

    #pragma unroll 1
    for (int c = 0; c < 16; ++c) {
        const int buf = c & 1;
        if (c + 1 < 16) {
            const int kk = (c + 1) * 16;
            a0 = *reinterpret_cast<const float4*>(arow + kk);
            a1 = *reinterpret_cast<const float4*>(arow + kk + 4);
            v00 = *reinterpret_cast<const float2*>(bcol + (size_t)(kk + 2 * kp0) * DOUT);
            v01 = *reinterpret_cast<const float2*>(bcol + (size_t)(kk + 2 * kp0 + 1) * DOUT);
            v10 = *reinterpret_cast<const float2*>(bcol + (size_t)(kk + 2 * kp0) * DOUT + 64);
            v11 = *reinterpret_cast<const float2*>(bcol + (size_t)(kk + 2 * kp0 + 1) * DOUT + 64);
        }
        #pragma unroll
        for (int kp = 0; kp < 8; kp++) {
            float2 a2[8], b2[8];
            #pragma unroll
            for (int i = 0; i < 4; i++) {
                float4 t = *reinterpret_cast<const float4*>(&As2[buf][kp][32 * i + 2 * ty]);
                a2[2 * i]     = make_float2(t.x, t.y);
                a2[2 * i + 1] = make_float2(t.z, t.w);
            }
            #pragma unroll
            for (int j = 0; j < 4; j++) {
                float4 t = *reinterpret_cast<const float4*>(&Bs2[buf][kp][32 * j + 2 * tx]);
                b2[2 * j]     = make_float2(t.x, t.y);
                b2[2 * j + 1] = make_float2(t.z, t.w);
            }
            #pragma unroll
            for (int i = 0; i < 8; i++)
                #pragma unroll
                for (int j = 0; j < 8; j++)
                    acc[i][j] = ffma2(a2[i], b2[j], acc[i][j]);
        }
        if (c + 1 < 16) {
            const int nb = buf ^ 1;
            As2[nb][4 * ha + 0][ra] = make_float2(a0.x, a0.y);
            As2[nb][4 * ha + 1][ra] = make_float2(a0.z, a0.w);
            As2[nb][4 * ha + 2][ra] = make_float2(a1.x, a1.y);
            As2[nb][4 * ha + 3][ra] = make_float2(a1.z, a1.w);
            *reinterpret_cast<float4*>(&Bs2[nb][kp0][2 * np0]) =
                make_float4(v00.x, v01.x, v00.y, v01.y);
            *reinterpret_cast<float4*>(&Bs2[nb][kp0][2 * np0 + 64]) =
                make_float4(v10.x, v11.x, v10.y, v11.y);
        }
        __syncthreads();
    }

    float bgv[8];
    #pragma unroll
    for (int u = 0; u < 4; u++) {
        bgv[2 * u]     = bout[j0v + 32 * u + 2 * tx];
        bgv[2 * u + 1] = bout[j0v + 32 * u + 2 * tx + 1];
    }
    #pragma unroll
    for (int i = 0; i < 8; i++) {
        const int m = m0 + 32 * (i >> 1) + 2 * ty + (i & 1);
        if (m < B_ * N) {
            float* crow = out + (size_t)m * DOUT + j0v;
            #pragma unroll
            for (int u = 0; u < 4; u++)
                *reinterpret_cast<float2*>(crow + 32 * u + 2 * tx) =
                    make_float2(
                        sigmoidf_(acc[i][2 * u].x + acc[i][2 * u].y + bgv[2 * u]),
                        sigmoidf_(acc[i][2 * u + 1].x + acc[i][2 * u + 1].y + bgv[2 * u + 1]));
        }
    }
}

// ---------------- Recurrence: persistent, batch-parallel, 4-CTA clusters ----------------
// Exact R9 structure (quarter-split GEMV, tx-counted mbarriers) with ONE change:
// h transport packs pairs of adjacent dims into st.async.b64 (one __shfl_down; even-pd
// lanes send). Messages per CTA per step: 512 -> 256; total tx bytes unchanged (2048).

__global__ __launch_bounds__(384, 1) __cluster_dims__(4, 1, 1)
void lstm_rec(
    const float* __restrict__ h0, const float* __restrict__ c0,
    const float* __restrict__ Wf, const float* __restrict__ Wi, const float* __restrict__ Wo,
    float* __restrict__ out, const int* __restrict__ Np)
{
    const int N   = *Np;
    const int r   = blockIdx.x & 3;
    const int cid = blockIdx.x >> 2;
    const int b0  = cid * 2;
    const int tid = threadIdx.x;

    __shared__ __align__(16) float h_s[2][2][256];   // [parity][batch][dim]
    __shared__ float pre_s[2][208];                  // [batch][col] (pad 208)
    __shared__ __align__(8) unsigned long long mbar[2];

    const int lane = tid & 31;
    const int wrp  = tid >> 5;
    const int kq   = lane & 3;                        // k-interleave slot
    const int cc0  = wrp * 16 + ((lane >> 2) << 1);   // first of 2 local gate-cols
    const int g0   = cc0 >> 6;
    const int gd0  = r * 64 + (cc0 & 63);
    const float* Wg = (g0 == 0) ? Wf : ((g0 == 1) ? Wi : Wo);

    // weights: w0/w1 = cols cc0/cc0+1; per line li: k0 = 4*kq + 16*li (h-part rows +256)
    float2 w0[32], w1[32];
    #pragma unroll
    for (int li = 0; li < 16; li++) {
        const int k0 = 4 * kq + 16 * li;
        const float* p0 = Wg + (size_t)(256 + k0) * DC + gd0;
        w0[2 * li]     = make_float2(p0[0],          p0[DC]);
        w0[2 * li + 1] = make_float2(p0[2 * DC],     p0[3 * DC]);
        w1[2 * li]     = make_float2(p0[1],          p0[DC + 1]);
        w1[2 * li + 1] = make_float2(p0[2 * DC + 1], p0[3 * DC + 1]);
    }

    // writer identity after reduction: lane kq ends with target (bw, cw)
    const int bw = kq >> 1;
    const int cw = cc0 + (kq & 1);
    const int gcolw = (cw >> 6) * 256 + r * 64 + (cw & 63);   // col in Gx layout [f|i|o]

    const uint32_t mb0 = smem_u32(&mbar[0]);
    const uint32_t mb1 = smem_u32(&mbar[1]);
    if (tid == 0) {
        mbar_init1(mb0);
        mbar_init1(mb1);
        mbar_expect(mb0, 2048);   // first use: h for step 2
        mbar_expect(mb1, 2048);   // first use: h for step 1
    }

    // init h (parity 0)
    for (int i = tid; i < 512; i += 384) {
        const int b = i >> 8, d = i & 255;
        h_s[0][b][d] = h0[(b0 + b) * DH + d];
    }
    float c_st = 0.f, h_loc = 0.f;
    const int pb = (tid < 128) ? (tid >> 6) : 0;
    const int pd = (tid < 128) ? (tid & 63) : 0;
    if (tid < 128) c_st = c0[(b0 + pb) * DC + r * 64 + pd];
    __syncthreads();
    cluster_sync_();   // all mbarriers initialized before any DSMEM traffic

    float gx = g_Gx[((size_t)(b0 + bw) * N + 0) * G3 + gcolw];

    float* out_hf = out + (size_t)B_ * N * DOUT;
    float* out_cf = out_hf + B_ * DH;

    int ph0 = 0, ph1 = 0;

    for (int t = 0; t < N; t++) {
        const int p = t & 1;

        if (t > 0) {
            const uint32_t mb = p ? mb1 : mb0;
            mbar_wait(mb, (uint32_t)(p ? ph1 : ph0));
            if (p) ph1 ^= 1; else ph0 ^= 1;
            if (tid == 0) mbar_expect(mb, 2048);   // re-arm for step t+2
        }

        const float gxc = gx;
        const int tn = (t + 1 < N) ? (t + 1) : t;
        gx = g_Gx[((size_t)(b0 + bw) * N + tn) * G3 + gcolw];

        // GEMV: acc[col][batch], h lines at byte offset kq*16 + li*64
        float2 a00 = make_float2(0.f, 0.f), a10 = a00, a01 = a00, a11 = a00;
        {
            const float4* hp0 = reinterpret_cast<const float4*>(&h_s[p][0][4 * kq]);
            const float4* hp1 = reinterpret_cast<const float4*>(&h_s[p][1][4 * kq]);
            #pragma unroll
            for (int li = 0; li < 16; li++) {
                float4 hv = hp0[4 * li];
                float2 hlo = make_float2(hv.x, hv.y), hhi = make_float2(hv.z, hv.w);
                a00 = ffma2(hlo, w0[2 * li], a00);
                a00 = ffma2(hhi, w0[2 * li + 1], a00);
                a10 = ffma2(hlo, w1[2 * li], a10);
                a10 = ffma2(hhi, w1[2 * li + 1], a10);
            }
            #pragma unroll
            for (int li = 0; li < 16; li++) {
                float4 hv = hp1[4 * li];
                float2 hlo = make_float2(hv.x, hv.y), hhi = make_float2(hv.z, hv.w);
                a01 = ffma2(hlo, w0[2 * li], a01);
                a01 = ffma2(hhi, w0[2 * li + 1], a01);
                a11 = ffma2(hlo, w1[2 * li], a11);
                a11 = ffma2(hhi, w1[2 * li + 1], a11);
            }
        }
        // targets: 0=(b0,c0) 1=(b0,c1) 2=(b1,c0) 3=(b1,c1)
        const float v0 = a00.x + a00.y;
        const float v1 = a10.x + a10.y;
        const float v2 = a01.x + a01.y;
        const float v3 = a11.x + a11.y;

        const bool bit0 = (kq & 1), bit1 = (kq & 2);
        // round 1 (xor 1): combine kq-pairs; packed send/keep
        float sendA = bit0 ? v0 : v1, keepA = bit0 ? v1 : v0;
        float tA = keepA + __shfl_xor_sync(0xffffffffu, sendA, 1);
        float sendB = bit0 ? v2 : v3, keepB = bit0 ? v3 : v2;
        float tB = keepB + __shfl_xor_sync(0xffffffffu, sendB, 1);
        // round 2 (xor 2): combine kq-half-pairs
        float send2 = bit1 ? tA : tB, keep2 = bit1 ? tB : tA;
        float sfin = keep2 + __shfl_xor_sync(0xffffffffu, send2, 2);

        pre_s[bw][cw] = sfin + gxc;
        __syncthreads();

        if (tid < 128) {
            const float pf = pre_s[pb][pd];
            const float pi = pre_s[pb][64 + pd];
            const float po = pre_s[pb][128 + pd];
            const float f  = sigmoidf_(pf);
            const float ig = sigmoidf_(pi);
            const float z  = tanhf_(pi);
            const float o  = sigmoidf_(po);
            c_st  = c_st * f + z * ig;
            h_loc = tanhf_(c_st) * o;

            if (t + 1 < N) {
                // pack adjacent-dim pair into one b64 message (pd is lane-consecutive)
                const float hn = __shfl_down_sync(0xffffffffu, h_loc, 1);
                if ((pd & 1) == 0) {
                    unsigned long long pkt;
                    asm("mov.b64 %0, {%1, %2};"
                        : "=l"(pkt)
                        : "r"(__float_as_uint(h_loc)), "r"(__float_as_uint(hn)));
                    const uint32_t la = smem_u32(&h_s[1 - p][pb][r * 64 + pd]);
                    const uint32_t lb = p ? mb0 : mb1;
                    st_async_remote64(la, lb, 0u, pkt);
                    st_async_remote64(la, lb, 1u, pkt);
                    st_async_remote64(la, lb, 2u, pkt);
                    st_async_remote64(la, lb, 3u, pkt);
                }
            }
            g_H[((size_t)(b0 + pb) * N + t) * DH + r * 64 + pd] = h_loc;
        }
    }

    if (tid < 128) {
        out_hf[(b0 + pb) * DH + r * 64 + pd] = h_loc;
        out_cf[(b0 + pb) * DC + r * 64 + pd] = c_st;
    }
    cluster_sync_();   // no CTA exits while peers could still be mid-step
}

// ---------------- launch ----------------

extern "C" void kernel_launch(void* const* d_in, const int* in_sizes, int n_in,
                              void* d_out, int out_size) {
    const float* x    = (const float*)d_in[0];
    const float* h0   = (const float*)d_in[1];
    const float* c0   = (const float*)d_in[2];
    const float* Wf   = (const float*)d_in[3];
    const float* bfp  = (const float*)d_in[4];
    const float* Wi   = (const float*)d_in[5];
    const float* bip  = (const float*)d_in[6];
    const float* Wo   = (const float*)d_in[7];
    const float* bop  = (const float*)d_in[8];
    const float* Wout = (const float*)d_in[9];
    const float* bout = (const float*)d_in[10];
    const int*   Np   = (const int*)d_in[11];
    float* out = (float*)d_out;

    dim3 g1(G3 / 128, B_ * T_ / 128);
    gemm_gx<<<g1, 256>>>(x, Wf, Wi, Wo, bfp, bip, bop, Np);

    lstm_rec<<<128, 384>>>(h0, c0, Wf, Wi, Wo, out, Np);

    dim3 g3(DOUT / 128, B_ * T_ / 128);
    gemm_out<<<g3, 256>>>(Wout, bout, out, Np);
}

// round 16
// speedup vs baseline: 1.2617x; 1.1743x over previous
#include <cuda_runtime.h>
#include <cstdint>

#define B_    64
#define T_    2048
#define DIN   256
#define DH    256
#define DC    256
#define DOUT  256
#define G3    768   // 3 gates * 256

// Scratch (allocation-free rule: __device__ globals)
__device__ float g_Gx[(size_t)B_ * T_ * G3];  // x-part gate preactivations (+bias)
__device__ float g_H [(size_t)B_ * T_ * DH];  // h_t for all t (for output GEMM)

// ---------------- helpers ----------------

__device__ __forceinline__ float2 ffma2(float2 a, float2 b, float2 c) {
    union U { float2 f; unsigned long long u; };
    U ua, ub, uc, ud;
    ua.f = a; ub.f = b; uc.f = c;
    asm("fma.rn.f32x2 %0, %1, %2, %3;"
        : "=l"(ud.u) : "l"(ua.u), "l"(ub.u), "l"(uc.u));
    return ud.f;
}

__device__ __forceinline__ uint32_t smem_u32(const void* p) {
    uint32_t a;
    asm("{ .reg .u64 t; cvta.to.shared.u64 t, %1; cvt.u32.u64 %0, t; }"
        : "=r"(a) : "l"(p));
    return a;
}

__device__ __forceinline__ void cluster_sync_() {
    asm volatile("barrier.cluster.arrive.aligned;" ::: "memory");
    asm volatile("barrier.cluster.wait.aligned;" ::: "memory");
}

__device__ __forceinline__ void mbar_init1(uint32_t mbar) {
    asm volatile("mbarrier.init.shared.b64 [%0], %1;" :: "r"(mbar), "r"(1u) : "memory");
}

__device__ __forceinline__ void mbar_expect(uint32_t mbar, uint32_t bytes) {
    asm volatile("mbarrier.arrive.expect_tx.shared.b64 _, [%0], %1;"
                 :: "r"(mbar), "r"(bytes) : "memory");
}

__device__ __forceinline__ void mbar_wait(uint32_t mbar, uint32_t parity) {
    asm volatile(
        "{\n\t"
        ".reg .pred P;\n"
        "W%=:\n\t"
        "mbarrier.try_wait.parity.acquire.cta.shared::cta.b64 P, [%0], %1, 0x989680;\n\t"
        "@P bra.uni D%=;\n\t"
        "bra.uni W%=;\n"
        "D%=:\n\t"
        "}"
        :: "r"(mbar), "r"(parity) : "memory");
}

// store one f32 into rank's smem + count 4 tx bytes on that rank's mbarrier
__device__ __forceinline__ void st_async_remote(uint32_t laddr, uint32_t lmbar,
                                                uint32_t rank, float v) {
    asm volatile(
        "{\n\t"
        ".reg .b32 ra, rb;\n\t"
        "mapa.shared::cluster.u32 ra, %0, %2;\n\t"
        "mapa.shared::cluster.u32 rb, %1, %2;\n\t"
        "st.async.shared::cluster.mbarrier::complete_tx::bytes.b32 [ra], %3, [rb];\n\t"
        "}"
        :: "r"(laddr), "r"(lmbar), "r"(rank), "r"(__float_as_uint(v)) : "memory");
}

__device__ __forceinline__ float sigmoidf_(float x) {
    return __fdividef(1.0f, 1.0f + __expf(-x));
}

__device__ __forceinline__ float tanhf_(float x) {
    return 1.0f - __fdividef(2.0f, 1.0f + __expf(2.0f * x));
}

// ================= GEMM core: 128x128 tile, BK=16, double-buffered (R9 proven) =======

__global__ __launch_bounds__(256) void gemm_gx(
    const float* __restrict__ X,
    const float* __restrict__ Wf, const float* __restrict__ Wi, const float* __restrict__ Wo,
    const float* __restrict__ bf, const float* __restrict__ bi, const float* __restrict__ bo,
    const int* __restrict__ Np)
{
    const int N = *Np;
    const int m0 = blockIdx.y * 128;
    if (m0 >= B_ * N) return;
    const int j0v = blockIdx.x * 128;
    const int g  = j0v >> 8;
    const int d0 = j0v & 255;
    const float* Wg = (g == 0) ? Wf : ((g == 1) ? Wi : Wo);
    const float* bg = (g == 0) ? bf : ((g == 1) ? bi : bo);

    __shared__ float2 As2[2][8][128];
    __shared__ float2 Bs2[2][8][128];

    const int tid = threadIdx.x;
    const int tx = tid & 15, ty = tid >> 4;

    const int ra = tid >> 1, ha = tid & 1;
    int mg = m0 + ra; if (mg >= B_ * N) mg = B_ * N - 1;
    const int bb = mg / N, tt = mg % N;
    const float* arow = X + (size_t)(bb * T_ + tt) * DIN + 8 * ha;

    const int kp0 = tid >> 5;
    const int np0 = tid & 31;
    const float* bcol = Wg + d0 + 2 * np0;

    float4 a0, a1;
    float2 v00, v01, v10, v11;

    a0 = *reinterpret_cast<const float4*>(arow);
    a1 = *reinterpret_cast<const float4*>(arow + 4);
    v00 = *reinterpret_cast<const float2*>(bcol + (size_t)(2 * kp0) * DC);
    v01 = *reinterpret_cast<const float2*>(bcol + (size_t)(2 * kp0 + 1) * DC);
    v10 = *reinterpret_cast<const float2*>(bcol + (size_t)(2 * kp0) * DC + 64);
    v11 = *reinterpret_cast<const float2*>(bcol + (size_t)(2 * kp0 + 1) * DC + 64);

    As2[0][4 * ha + 0][ra] = make_float2(a0.x, a0.y);
    As2[0][4 * ha + 1][ra] = make_float2(a0.z, a0.w);
    As2[0][4 * ha + 2][ra] = make_float2(a1.x, a1.y);
    As2[0][4 * ha + 3][ra] = make_float2(a1.z, a1.w);
    *reinterpret_cast<float4*>(&Bs2[0][kp0][2 * np0]) =
        make_float4(v00.x, v01.x, v00.y, v01.y);
    *reinterpret_cast<float4*>(&Bs2[0][kp0][2 * np0 + 64]) =
        make_float4(v10.x, v11.x, v10.y, v11.y);
    __syncthreads();

    float2 acc[8][8];
    #pragma unroll
    for (int i = 0; i < 8; i++)
        #pragma unroll
        for (int j = 0; j < 8; j++) acc[i][j] = make_float2(0.f, 0.f);

    #pragma unroll 1
    for (int c = 0; c < 16; ++c) {
        const int buf = c & 1;
        if (c + 1 < 16) {
            const int kk = (c + 1) * 16;
            a0 = *reinterpret_cast<const float4*>(arow + kk);
            a1 = *reinterpret_cast<const float4*>(arow + kk + 4);
            v00 = *reinterpret_cast<const float2*>(bcol + (size_t)(kk + 2 * kp0) * DC);
            v01 = *reinterpret_cast<const float2*>(bcol + (size_t)(kk + 2 * kp0 + 1) * DC);
            v10 = *reinterpret_cast<const float2*>(bcol + (size_t)(kk + 2 * kp0) * DC + 64);
            v11 = *reinterpret_cast<const float2*>(bcol + (size_t)(kk + 2 * kp0 + 1) * DC + 64);
        }
        #pragma unroll
        for (int kp = 0; kp < 8; kp++) {
            float2 a2[8], b2[8];
            #pragma unroll
            for (int i = 0; i < 4; i++) {
                float4 t = *reinterpret_cast<const float4*>(&As2[buf][kp][32 * i + 2 * ty]);
                a2[2 * i]     = make_float2(t.x, t.y);
                a2[2 * i + 1] = make_float2(t.z, t.w);
            }
            #pragma unroll
            for (int j = 0; j < 4; j++) {
                float4 t = *reinterpret_cast<const float4*>(&Bs2[buf][kp][32 * j + 2 * tx]);
                b2[2 * j]     = make_float2(t.x, t.y);
                b2[2 * j + 1] = make_float2(t.z, t.w);
            }
            #pragma unroll
            for (int i = 0; i < 8; i++)
                #pragma unroll
                for (int j = 0; j < 8; j++)
                    acc[i][j] = ffma2(a2[i], b2[j], acc[i][j]);
        }
        if (c + 1 < 16) {
            const int nb = buf ^ 1;
            As2[nb][4 * ha + 0][ra] = make_float2(a0.x, a0.y);
            As2[nb][4 * ha + 1][ra] = make_float2(a0.z, a0.w);
            As2[nb][4 * ha + 2][ra] = make_float2(a1.x, a1.y);
            As2[nb][4 * ha + 3][ra] = make_float2(a1.z, a1.w);
            *reinterpret_cast<float4*>(&Bs2[nb][kp0][2 * np0]) =
                make_float4(v00.x, v01.x, v00.y, v01.y);
            *reinterpret_cast<float4*>(&Bs2[nb][kp0][2 * np0 + 64]) =
                make_float4(v10.x, v11.x, v10.y, v11.y);
        }
        __syncthreads();
    }

    float bgv[8];
    #pragma unroll
    for (int u = 0; u < 4; u++) {
        bgv[2 * u]     = bg[d0 + 32 * u + 2 * tx];
        bgv[2 * u + 1] = bg[d0 + 32 * u + 2 * tx + 1];
    }
    #pragma unroll
    for (int i = 0; i < 8; i++) {
        const int m = m0 + 32 * (i >> 1) + 2 * ty + (i & 1);
        if (m < B_ * N) {
            float* crow = g_Gx + (size_t)m * G3 + j0v;
            #pragma unroll
            for (int u = 0; u < 4; u++)
                *reinterpret_cast<float2*>(crow + 32 * u + 2 * tx) =
                    make_float2(acc[i][2 * u].x + acc[i][2 * u].y + bgv[2 * u],
                                acc[i][2 * u + 1].x + acc[i][2 * u + 1].y + bgv[2 * u + 1]);
        }
    }
}

// ---------------- GEMM 3: outs = sigmoid(H @ Wout + bout) ----------------

__global__ __launch_bounds__(256) void gemm_out(
    const float* __restrict__ Wout, const float* __restrict__ bout,
    float* __restrict__ out, const int* __restrict__ Np)
{
    const int N = *Np;
    const int m0 = blockIdx.y * 128;
    if (m0 >= B_ * N) return;
    const int j0v = blockIdx.x * 128;

    __shared__ float2 As2[2][8][128];
    __shared__ float2 Bs2[2][8][128];

    const int tid = threadIdx.x;
    const int tx = tid & 15, ty = tid >> 4;

    const int ra = tid >> 1, ha = tid & 1;
    int mg = m0 + ra; if (mg >= B_ * N) mg = B_ * N - 1;
    const float* arow = g_H + (size_t)mg * DH + 8 * ha;

    const int kp0 = tid >> 5;
    const int np0 = tid & 31;
    const float* bcol = Wout + j0v + 2 * np0;

    float4 a0, a1;
    float2 v00, v01, v10, v11;

    a0 = *reinterpret_cast<const float4*>(arow);
    a1 = *reinterpret_cast<const float4*>(arow + 4);
    v00 = *reinterpret_cast<const float2*>(bcol + (size_t)(2 * kp0) * DOUT);
    v01 = *reinterpret_cast<const float2*>(bcol + (size_t)(2 * kp0 + 1) * DOUT);
    v10 = *reinterpret_cast<const float2*>(bcol + (size_t)(2 * kp0) * DOUT + 64);
    v11 = *reinterpret_cast<const float2*>(bcol + (size_t)(2 * kp0 + 1) * DOUT + 64);

    As2[0][4 * ha + 0][ra] = make_float2(a0.x, a0.y);
    As2[0][4 * ha + 1][ra] = make_float2(a0.z, a0.w);
    As2[0][4 * ha + 2][ra] = make_float2(a1.x, a1.y);
    As2[0][4 * ha + 3][ra] = make_float2(a1.z, a1.w);
    *reinterpret_cast<float4*>(&Bs2[0][kp0][2 * np0]) =
        make_float4(v00.x, v01.x, v00.y, v01.y);
    *reinterpret_cast<float4*>(&Bs2[0][kp0][2 * np0 + 64]) =
        make_float4(v10.x, v11.x, v10.y, v11.y);
    __syncthreads();

    float2 acc[8][8];
    #pragma unroll
    for (int i = 0; i < 8; i++)
        #pragma unroll
        for (int j = 0; j < 8; j++) acc[i][j] = make_float2(0.f, 0.f);

    #pragma unroll 1
    for (int c = 0; c < 16; ++c) {
        const int buf = c & 1;
        if (c + 1 < 16) {
            const int kk = (c + 1) * 16;
            a0 = *reinterpret_cast<const float4*>(arow + kk);
            a1 = *reinterpret_cast<const float4*>(arow + kk + 4);
            v00 = *reinterpret_cast<const float2*>(bcol + (size_t)(kk + 2 * kp0) * DOUT);
            v01 = *reinterpret_cast<const float2*>(bcol + (size_t)(kk + 2 * kp0 + 1) * DOUT);
            v10 = *reinterpret_cast<const float2*>(bcol + (size_t)(kk + 2 * kp0) * DOUT + 64);
            v11 = *reinterpret_cast<const float2*>(bcol + (size_t)(kk + 2 * kp0 + 1) * DOUT + 64);
        }
        #pragma unroll
        for (int kp = 0; kp < 8; kp++) {
            float2 a2[8], b2[8];
            #pragma unroll
            for (int i = 0; i < 4; i++) {
                float4 t = *reinterpret_cast<const float4*>(&As2[buf][kp][32 * i + 2 * ty]);
                a2[2 * i]     = make_float2(t.x, t.y);
                a2[2 * i + 1] = make_float2(t.z, t.w);
            }
            #pragma unroll
            for (int j = 0; j < 4; j++) {
                float4 t = *reinterpret_cast<const float4*>(&Bs2[buf][kp][32 * j + 2 * tx]);
                b2[2 * j]     = make_float2(t.x, t.y);
                b2[2 * j + 1] = make_float2(t.z, t.w);
            }
            #pragma unroll
            for (int i = 0; i < 8; i++)
                #pragma unroll
                for (int j = 0; j < 8; j++)
                    acc[i][j] = ffma2(a2[i], b2[j], acc[i][j]);
        }
        if (c + 1 < 16) {
            const int nb = buf ^ 1;
            As2[nb][4 * ha + 0][ra] = make_float2(a0.x, a0.y);
            As2[nb][4 * ha + 1][ra] = make_float2(a0.z, a0.w);
            As2[nb][4 * ha + 2][ra] = make_float2(a1.x, a1.y);
            As2[nb][4 * ha + 3][ra] = make_float2(a1.z, a1.w);
            *reinterpret_cast<float4*>(&Bs2[nb][kp0][2 * np0]) =
                make_float4(v00.x, v01.x, v00.y, v01.y);
            *reinterpret_cast<float4*>(&Bs2[nb][kp0][2 * np0 + 64]) =
                make_float4(v10.x, v11.x, v10.y, v11.y);
        }
        __syncthreads();
    }

    float bgv[8];
    #pragma unroll
    for (int u = 0; u < 4; u++) {
        bgv[2 * u]     = bout[j0v + 32 * u + 2 * tx];
        bgv[2 * u + 1] = bout[j0v + 32 * u + 2 * tx + 1];
    }
    #pragma unroll
    for (int i = 0; i < 8; i++) {
        const int m = m0 + 32 * (i >> 1) + 2 * ty + (i & 1);
        if (m < B_ * N) {
            float* crow = out + (size_t)m * DOUT + j0v;
            #pragma unroll
            for (int u = 0; u < 4; u++)
                *reinterpret_cast<float2*>(crow + 32 * u + 2 * tx) =
                    make_float2(
                        sigmoidf_(acc[i][2 * u].x + acc[i][2 * u].y + bgv[2 * u]),
                        sigmoidf_(acc[i][2 * u + 1].x + acc[i][2 * u + 1].y + bgv[2 * u + 1]));
        }
    }
}

// ---------------- Recurrence: persistent, batch-parallel, 4-CTA clusters ----------------
// R9 structure (quarter-split GEMV, per-lane st.async.b32) with split-wait:
//  * weight lines loaded rank-permuted so GEMV lines j=0..3 are the OWN rank's k-chunk
//  * own h chunk delivered locally (STS + loop-end __syncthreads), remote via st.async
//    to 3 peers (expect_tx 1536)
//  * per step: part-1 GEMV (own chunk) runs BEFORE the mbar wait, hiding the DSMEM
//    delivery latency of the 3 remote chunks; part-2 GEMV after the wait.

__global__ __launch_bounds__(384, 1) __cluster_dims__(4, 1, 1)
void lstm_rec(
    const float* __restrict__ h0, const float* __restrict__ c0,
    const float* __restrict__ Wf, const float* __restrict__ Wi, const float* __restrict__ Wo,
    float* __restrict__ out, const int* __restrict__ Np)
{
    const int N   = *Np;
    const int r   = blockIdx.x & 3;
    const int cid = blockIdx.x >> 2;
    const int b0  = cid * 2;
    const int tid = threadIdx.x;

    __shared__ __align__(16) float h_s[2][2][256];   // [parity][batch][dim]
    __shared__ float pre_s[2][208];                  // [batch][col] (pad 208)
    __shared__ __align__(8) unsigned long long mbar[2];

    const int lane = tid & 31;
    const int wrp  = tid >> 5;
    const int kq   = lane & 3;                        // k-interleave slot
    const int cc0  = wrp * 16 + ((lane >> 2) << 1);   // first of 2 local gate-cols
    const int g0   = cc0 >> 6;
    const int gd0  = r * 64 + (cc0 & 63);
    const float* Wg = (g0 == 0) ? Wf : ((g0 == 1) ? Wi : Wo);

    // weights in rank-permuted line order: slot j uses line li=(j+4r)&15, so slots
    // 0..3 are the own-rank k-chunk. loff[j] = float4-offset of line li in h_s rows.
    float2 w0[32], w1[32];
    int loff[16];
    #pragma unroll
    for (int j = 0; j < 16; j++) {
        const int li = (j + 4 * r) & 15;
        loff[j] = 4 * li;
        const int k0 = 4 * kq + 16 * li;
        const float* p0 = Wg + (size_t)(256 + k0) * DC + gd0;
        w0[2 * j]     = make_float2(p0[0],          p0[DC]);
        w0[2 * j + 1] = make_float2(p0[2 * DC],     p0[3 * DC]);
        w1[2 * j]     = make_float2(p0[1],          p0[DC + 1]);
        w1[2 * j + 1] = make_float2(p0[2 * DC + 1], p0[3 * DC + 1]);
    }

    // writer identity after reduction: lane kq ends with target (bw, cw)
    const int bw = kq >> 1;
    const int cw = cc0 + (kq & 1);
    const int gcolw = (cw >> 6) * 256 + r * 64 + (cw & 63);   // col in Gx layout [f|i|o]

    const uint32_t mb0 = smem_u32(&mbar[0]);
    const uint32_t mb1 = smem_u32(&mbar[1]);
    if (tid == 0) {
        mbar_init1(mb0);
        mbar_init1(mb1);
        mbar_expect(mb0, 1536);   // first use: remote h for step 2
        mbar_expect(mb1, 1536);   // first use: remote h for step 1
    }

    // init h (parity 0)
    for (int i = tid; i < 512; i += 384) {
        const int b = i >> 8, d = i & 255;
        h_s[0][b][d] = h0[(b0 + b) * DH + d];
    }
    float c_st = 0.f, h_loc = 0.f;
    const int pb = (tid < 128) ? (tid >> 6) : 0;
    const int pd = (tid < 128) ? (tid & 63) : 0;
    if (tid < 128) c_st = c0[(b0 + pb) * DC + r * 64 + pd];
    __syncthreads();
    cluster_sync_();   // all mbarriers initialized before any DSMEM traffic

    float gx = g_Gx[((size_t)(b0 + bw) * N + 0) * G3 + gcolw];

    float* out_hf = out + (size_t)B_ * N * DOUT;
    float* out_cf = out_hf + B_ * DH;

    int ph0 = 0, ph1 = 0;

    for (int t = 0; t < N; t++) {
        const int p = t & 1;

        const float gxc = gx;
        const int tn = (t + 1 < N) ? (t + 1) : t;
        gx = g_Gx[((size_t)(b0 + bw) * N + tn) * G3 + gcolw];

        const float4* hp0 = reinterpret_cast<const float4*>(&h_s[p][0][4 * kq]);
        const float4* hp1 = reinterpret_cast<const float4*>(&h_s[p][1][4 * kq]);

        float2 a00 = make_float2(0.f, 0.f), a10 = a00, a01 = a00, a11 = a00;

        // ---- part 1: OWN rank chunk (slots 0..3) — no wait needed (local STS) ----
        #pragma unroll
        for (int j = 0; j < 4; j++) {
            float4 hv = hp0[loff[j]];
            float2 hlo = make_float2(hv.x, hv.y), hhi = make_float2(hv.z, hv.w);
            a00 = ffma2(hlo, w0[2 * j], a00);
            a00 = ffma2(hhi, w0[2 * j + 1], a00);
            a10 = ffma2(hlo, w1[2 * j], a10);
            a10 = ffma2(hhi, w1[2 * j + 1], a10);
            float4 hw = hp1[loff[j]];
            float2 glo = make_float2(hw.x, hw.y), ghi = make_float2(hw.z, hw.w);
            a01 = ffma2(glo, w0[2 * j], a01);
            a01 = ffma2(ghi, w0[2 * j + 1], a01);
            a11 = ffma2(glo, w1[2 * j], a11);
            a11 = ffma2(ghi, w1[2 * j + 1], a11);
        }

        // ---- wait for the 3 remote chunks ----
        if (t > 0) {
            const uint32_t mb = p ? mb1 : mb0;
            mbar_wait(mb, (uint32_t)(p ? ph1 : ph0));
            if (p) ph1 ^= 1; else ph0 ^= 1;
            if (tid == 0) mbar_expect(mb, 1536);   // re-arm for step t+2
        }

        // ---- part 2: remote chunks (slots 4..15) ----
        #pragma unroll
        for (int j = 4; j < 16; j++) {
            float4 hv = hp0[loff[j]];
            float2 hlo = make_float2(hv.x, hv.y), hhi = make_float2(hv.z, hv.w);
            a00 = ffma2(hlo, w0[2 * j], a00);
            a00 = ffma2(hhi, w0[2 * j + 1], a00);
            a10 = ffma2(hlo, w1[2 * j], a10);
            a10 = ffma2(hhi, w1[2 * j + 1], a10);
            float4 hw = hp1[loff[j]];
            float2 glo = make_float2(hw.x, hw.y), ghi = make_float2(hw.z, hw.w);
            a01 = ffma2(glo, w0[2 * j], a01);
            a01 = ffma2(ghi, w0[2 * j + 1], a01);
            a11 = ffma2(glo, w1[2 * j], a11);
            a11 = ffma2(ghi, w1[2 * j + 1], a11);
        }

        // targets: 0=(b0,c0) 1=(b0,c1) 2=(b1,c0) 3=(b1,c1)
        const float v0 = a00.x + a00.y;
        const float v1 = a10.x + a10.y;
        const float v2 = a01.x + a01.y;
        const float v3 = a11.x + a11.y;

        const bool bit0 = (kq & 1), bit1 = (kq & 2);
        float sendA = bit0 ? v0 : v1, keepA = bit0 ? v1 : v0;
        float tA = keepA + __shfl_xor_sync(0xffffffffu, sendA, 1);
        float sendB = bit0 ? v2 : v3, keepB = bit0 ? v3 : v2;
        float tB = keepB + __shfl_xor_sync(0xffffffffu, sendB, 1);
        float send2 = bit1 ? tA : tB, keep2 = bit1 ? tB : tA;
        float sfin = keep2 + __shfl_xor_sync(0xffffffffu, send2, 2);

        pre_s[bw][cw] = sfin + gxc;
        __syncthreads();

        if (tid < 128) {
            const float pf = pre_s[pb][pd];
            const float pi = pre_s[pb][64 + pd];
            const float po = pre_s[pb][128 + pd];
            const float f  = sigmoidf_(pf);
            const float ig = sigmoidf_(pi);
            const float z  = tanhf_(pi);
            const float o  = sigmoidf_(po);
            c_st  = c_st * f + z * ig;
            h_loc = tanhf_(c_st) * o;

            if (t + 1 < N) {
                // own chunk: local STS (visible via loop-end __syncthreads);
                // remote: st.async to the 3 peer ranks (tx-counted on their mbar)
                h_s[1 - p][pb][r * 64 + pd] = h_loc;
                const uint32_t la = smem_u32(&h_s[1 - p][pb][r * 64 + pd]);
                const uint32_t lb = p ? mb0 : mb1;
                st_async_remote(la, lb, (r + 1) & 3, h_loc);
                st_async_remote(la, lb, (r + 2) & 3, h_loc);
                st_async_remote(la, lb, (r + 3) & 3, h_loc);
            }
            g_H[((size_t)(b0 + pb) * N + t) * DH + r * 64 + pd] = h_loc;
        }
        __syncthreads();   // local own-chunk h visible for next step's part-1
    }

    if (tid < 128) {
        out_hf[(b0 + pb) * DH + r * 64 + pd] = h_loc;
        out_cf[(b0 + pb) * DC + r * 64 + pd] = c_st;
    }
    cluster_sync_();   // no CTA exits while peers could still be mid-step
}

// ---------------- launch ----------------

extern "C" void kernel_launch(void* const* d_in, const int* in_sizes, int n_in,
                              void* d_out, int out_size) {
    const float* x    = (const float*)d_in[0];
    const float* h0   = (const float*)d_in[1];
    const float* c0   = (const float*)d_in[2];
    const float* Wf   = (const float*)d_in[3];
    const float* bfp  = (const float*)d_in[4];
    const float* Wi   = (const float*)d_in[5];
    const float* bip  = (const float*)d_in[6];
    const float* Wo   = (const float*)d_in[7];
    const float* bop  = (const float*)d_in[8];
    const float* Wout = (const float*)d_in[9];
    const float* bout = (const float*)d_in[10];
    const int*   Np   = (const int*)d_in[11];
    float* out = (float*)d_out;

    dim3 g1(G3 / 128, B_ * T_ / 128);
    gemm_gx<<<g1, 256>>>(x, Wf, Wi, Wo, bfp, bip, bop, Np);

    lstm_rec<<<128, 384>>>(h0, c0, Wf, Wi, Wo, out, Np);

    dim3 g3(DOUT / 128, B_ * T_ / 128);
    gemm_out<<<g3, 256>>>(Wout, bout, out, Np);
}